// round 7
// baseline (speedup 1.0000x reference)
#include <cuda_runtime.h>
#include <math.h>

#define H_IN   192
#define W_IN   192
#define HOUT   96
#define WOUT   96
#define C1     32
#define NN     17
#define BATCH  128

#define TS     32          // output tile 32x32; 4 px/thread (8 quads x 32 rows)
#define HTS    34          // h tile dim (TS + 2 halo)
#define HSTR   36          // h row stride (floats) -> rows 144B
#define SMH1   (HTS*HSTR)  // 1224 floats per channel
#define ITS    69          // input tile dim (2*TS + 5)
#define ISTR   72          // input row stride
#define NP     5           // max conv1 positions per thread (ceil(1156/256))
#define WROW   36          // splatted weight row: 17 pairs (34 f) padded to 36

#define SM_W1T (C1*12)          // 384   floats (transposed W1, rows padded 9->12)
#define SM_IN  (ITS*ISTR)       // 4968  floats
#define SM_H   (C1*SMH1)        // 39168 floats
#define SM_W2  (9*C1*WROW)      // 10368 floats (splatted {w,w} pairs)
#define SM_FLOATS (SM_W1T + SM_IN + SM_H + SM_W2)
#define SM_BYTES  (SM_FLOATS * 4)    // 219,552 B (< 227KB)

__constant__ float cB1[C1];
__constant__ float cB2[NN];

__device__ float g_cms[(size_t)BATCH*NN*HOUT*WOUT];
__device__ unsigned long long g_peak[BATCH*NN];

typedef unsigned long long ull;

static __device__ __forceinline__ ull pk2(float lo, float hi) {
    ull r; asm("mov.b64 %0,{%1,%2};" : "=l"(r) : "f"(lo), "f"(hi)); return r;
}
static __device__ __forceinline__ void upk2(ull v, float& lo, float& hi) {
    asm("mov.b64 {%0,%1},%2;" : "=f"(lo), "=f"(hi) : "l"(v));
}
// packed 2-wide fp32 FMA — real dual-rate FFMA2 on sm_103a (PTX-only path)
static __device__ __forceinline__ ull ffma2(ull a, ull b, ull c) {
    ull d; asm("fma.rn.f32x2 %0,%1,%2,%3;" : "=l"(d) : "l"(a), "l"(b), "l"(c)); return d;
}
// monotonic (value desc, first-index) ordering key
static __device__ __forceinline__ ull pkkey(float v, unsigned idx) {
    unsigned k = __float_as_uint(v);
    k = (k & 0x80000000u) ? ~k : (k | 0x80000000u);
    return ((ull)k << 32) | (0xFFFFFFFFu - idx);
}

__global__ __launch_bounds__(256, 1)
void conv_fused_kernel(const float* __restrict__ crops,
                       const float* __restrict__ W1g,
                       const float* __restrict__ W2g)
{
    extern __shared__ float sm[];
    float* s_w1t = sm;                    // [C1][12]
    float* s_in  = sm + SM_W1T;           // [ITS][ISTR]
    float* s_h   = s_in + SM_IN;          // [C1][HTS][HSTR]
    float* s_w2  = s_h + SM_H;            // [9*C1][WROW] splatted pairs

    const int tid = threadIdx.x;
    const int x0  = blockIdx.x * TS;
    const int y0  = blockIdx.y * TS;
    const int b   = blockIdx.z;

    // stage transposed W1 (288 entries, strided over 256 threads)
    for (int i = tid; i < 9*C1; i += 256) {
        int k = i / C1, c = i - k*C1;
        s_w1t[c*12 + k] = W1g[i];
    }
    // stage W2 as splatted pairs: s_w2[kc][2n]=s_w2[kc][2n+1]=W2[kc][n]; pad = 0
    for (int i = tid; i < 9*C1*NN; i += 256) {
        int kc = i / NN, n = i - kc*NN;
        float w = W2g[i];
        s_w2[kc*WROW + 2*n]     = w;
        s_w2[kc*WROW + 2*n + 1] = w;
    }
    for (int i = tid; i < 9*C1; i += 256) { s_w2[i*WROW+34] = 0.f; s_w2[i*WROW+35] = 0.f; }

    // stage input tile (rows 2*y0-2 .. 2*y0+66)
    const float* img = crops + (size_t)b * H_IN * W_IN;
    for (int i = tid; i < ITS*ITS; i += 256) {
        int r  = i / ITS, cc = i - r*ITS;
        int iy = 2*y0 - 2 + r;
        int ix = 2*x0 - 2 + cc;
        float v = 0.f;
        if (iy >= 0 && iy < H_IN && ix >= 0 && ix < W_IN) v = img[iy*W_IN + ix];
        s_in[r*ISTR + cc] = v;
    }
    __syncthreads();

    // ================= conv1: all 32 channels -> s_h =================
    float in9[NP][9];
    int   offh[NP];
    bool  pmask[NP], pborder[NP];
    #pragma unroll
    for (int i = 0; i < NP; i++) {
        int p = tid + i*256;
        pmask[i] = (p < HTS*HTS);
        int pp = pmask[i] ? p : 0;
        int ly = pp / HTS, lx = pp - ly*HTS;
        offh[i] = ly*HSTR + lx;
        int gy = y0 - 1 + ly, gx = x0 - 1 + lx;
        pborder[i] = (gy >= 0) & (gy < HOUT) & (gx >= 0) & (gx < WOUT);
        const float* r0 = s_in + (2*ly)*ISTR + 2*lx;
        #pragma unroll
        for (int ky = 0; ky < 3; ky++) {
            const float2 v2 = *(const float2*)(r0 + ky*ISTR);
            in9[i][ky*3+0] = v2.x;
            in9[i][ky*3+1] = v2.y;
            in9[i][ky*3+2] = r0[ky*ISTR + 2];
        }
    }
    #pragma unroll 1
    for (int c = 0; c < C1; c++) {
        const float4 wa = *(const float4*)(s_w1t + c*12);
        const float4 wb = *(const float4*)(s_w1t + c*12 + 4);
        const float  w8 = s_w1t[c*12 + 8];
        const float  b1c = cB1[c];
        float* hc = s_h + c*SMH1;
        #pragma unroll
        for (int i = 0; i < NP; i++) {
            if (!pmask[i]) continue;
            float a = b1c;
            a = fmaf(in9[i][0], wa.x, a);
            a = fmaf(in9[i][1], wa.y, a);
            a = fmaf(in9[i][2], wa.z, a);
            a = fmaf(in9[i][3], wa.w, a);
            a = fmaf(in9[i][4], wb.x, a);
            a = fmaf(in9[i][5], wb.y, a);
            a = fmaf(in9[i][6], wb.z, a);
            a = fmaf(in9[i][7], wb.w, a);
            a = fmaf(in9[i][8], w8,   a);
            a = fmaxf(a, 0.f);
            hc[offh[i]] = pborder[i] ? a : 0.f;
        }
    }
    __syncthreads();

    // ========== conv2 (packed f32x2): 4 px x 17 nodes per thread ==========
    const int txq = tid & 7;
    const int ty  = tid >> 3;

    ull accA[NN], accB[NN];     // A = (px0,px1), B = (px2,px3)
    #pragma unroll
    for (int n = 0; n < NN; n++) {
        ull bb = pk2(cB2[n], cB2[n]);
        accA[n] = bb; accB[n] = bb;
    }

    #pragma unroll 1
    for (int c = 0; c < C1; c++) {
        const float* hc = s_h + c*SMH1;
        #pragma unroll
        for (int dy = 0; dy < 3; dy++) {
            const float* hrow = hc + (ty + dy)*HSTR + 4*txq;     // 16B aligned
            const ulonglong2 hq = *(const ulonglong2*)hrow;      // (h0,h1),(h2,h3)
            const ull duo = *(const ull*)(hrow + 4);             // (h4,h5)
            const ull pA[3] = { hq.x, (hq.x >> 32) | (hq.y << 32), hq.y };
            const ull pB[3] = { hq.y, (hq.y >> 32) | (duo  << 32), duo  };
            #pragma unroll
            for (int dx = 0; dx < 3; dx++) {
                const ull* wp = (const ull*)(s_w2 + ((dy*3 + dx)*C1 + c)*WROW);
                const ull a = pA[dx], bo = pB[dx];
                #pragma unroll
                for (int n = 0; n < NN; n++) {
                    const ull w = wp[n];
                    accA[n] = ffma2(a,  w, accA[n]);
                    accB[n] = ffma2(bo, w, accB[n]);
                }
            }
        }
    }

    // ================= write cms + fused per-(b,n) argmax =================
    const int gy  = y0 + ty;
    const int gxb = x0 + 4*txq;
    float* outp = g_cms + (size_t)b*NN*HOUT*WOUT + (size_t)gy*WOUT + gxb;
    const unsigned basei = (unsigned)(gy*WOUT + gxb);

    ull* red = (ull*)s_in;                 // reuse; safe after conv1
    const int lane = tid & 31, wrp = tid >> 5;

    #pragma unroll
    for (int n = 0; n < NN; n++) {
        float v0, v1, v2, v3;
        upk2(accA[n], v0, v1);
        upk2(accB[n], v2, v3);
        *(float4*)(outp + (size_t)n*HOUT*WOUT) = make_float4(v0, v1, v2, v3);

        ull m = pkkey(v0, basei);
        ull t = pkkey(v1, basei+1); if (t > m) m = t;
        t = pkkey(v2, basei+2); if (t > m) m = t;
        t = pkkey(v3, basei+3); if (t > m) m = t;
        #pragma unroll
        for (int s = 16; s; s >>= 1) {
            ull o = __shfl_xor_sync(0xffffffffu, m, s);
            if (o > m) m = o;
        }
        if (lane == 0) red[n*8 + wrp] = m;
    }
    __syncthreads();
    if (tid < NN) {
        ull m = red[tid*8];
        #pragma unroll
        for (int w = 1; w < 8; w++) {
            ull o = red[tid*8 + w];
            if (o > m) m = o;
        }
        atomicMax(&g_peak[b*NN + tid], m);
    }
}

// decode winner, quarter-pixel refinement, threshold, x2 stride
__global__ void refine_kernel(float* __restrict__ out)
{
    int bn = blockIdx.x * 256 + threadIdx.x;
    if (bn >= BATCH*NN) return;
    ull p = g_peak[bn];
    unsigned idx = 0xFFFFFFFFu - (unsigned)(p & 0xFFFFFFFFu);
    int yi = idx / WOUT;
    int xi = idx - yi*WOUT;
    const float* cm = g_cms + (size_t)bn * HOUT * WOUT;
    float val = cm[idx];

    int xm = max(xi-1, 0), xp = min(xi+1, WOUT-1);
    int ym = max(yi-1, 0), yp = min(yi+1, HOUT-1);
    float ddx = cm[yi*WOUT + xp] - cm[yi*WOUT + xm];
    float ddy = cm[yp*WOUT + xi] - cm[ym*WOUT + xi];
    float sx = (ddx > 0.f) ? 1.f : ((ddx < 0.f) ? -1.f : 0.f);
    float sy = (ddy > 0.f) ? 1.f : ((ddy < 0.f) ? -1.f : 0.f);

    float px = ((float)xi + 0.25f*sx) * 2.0f;
    float py = ((float)yi + 0.25f*sy) * 2.0f;
    if (!(val >= 0.2f)) { px = nanf(""); py = nanf(""); }

    out[bn*3 + 0] = px;
    out[bn*3 + 1] = py;
    out[bn*3 + 2] = val;
}

extern "C" void kernel_launch(void* const* d_in, const int* in_sizes, int n_in,
                              void* d_out, int out_size)
{
    const float* crops = (const float*)d_in[0];
    const float* W1    = (const float*)d_in[1];
    const float* b1    = (const float*)d_in[2];
    const float* W2    = (const float*)d_in[3];
    const float* b2    = (const float*)d_in[4];
    float* out = (float*)d_out;

    cudaMemcpyToSymbolAsync(cB1, b1, C1*sizeof(float), 0, cudaMemcpyDeviceToDevice, 0);
    cudaMemcpyToSymbolAsync(cB2, b2, NN*sizeof(float), 0, cudaMemcpyDeviceToDevice, 0);

    void* peak_ptr = nullptr;
    cudaGetSymbolAddress(&peak_ptr, g_peak);
    cudaMemsetAsync(peak_ptr, 0, BATCH*NN*sizeof(ull), 0);

    cudaFuncSetAttribute(conv_fused_kernel,
                         cudaFuncAttributeMaxDynamicSharedMemorySize, SM_BYTES);

    dim3 grid(WOUT/TS, HOUT/TS, BATCH);
    conv_fused_kernel<<<grid, 256, SM_BYTES>>>(crops, W1, W2);

    refine_kernel<<<(BATCH*NN + 255)/256, 256>>>(out);
}